// round 14
// baseline (speedup 1.0000x reference)
#include <cuda_runtime.h>

#define N 8192
#define BB 2
#define CH 64
#define KNB 16
#define FULLMASK 0xffffffffu
typedef unsigned long long ull;
typedef unsigned int uint;

// ---------------- scratch (static device globals; no allocation) ----------------
__device__ float g_q1[BB*N*CH];
__device__ float g_q2[BB*N*CH];
__device__ float g_r1[BB*N*CH];
__device__ float g_r2[BB*N*CH];
__device__ float g_f1[BB*N*CH];
__device__ float g_f2[BB*N*CH];
__device__ int   g_i12[BB*N*KNB];
__device__ int   g_i21[BB*N*KNB];

__device__ __forceinline__ float leaky(float x) { return fmaxf(x, 0.1f * x); }

// ---------------- packed f32x2 helpers ----------------
__device__ __forceinline__ ull ffma2(ull a, ull b, ull c) {
    ull d; asm("fma.rn.f32x2 %0, %1, %2, %3;" : "=l"(d) : "l"(a), "l"(b), "l"(c)); return d;
}
__device__ __forceinline__ ull pk2(float x, float y) {
    ull r; asm("mov.b64 %0, {%1, %2};" : "=l"(r) : "f"(x), "f"(y)); return r;
}
__device__ __forceinline__ ull dup2(float x) {
    ull r; asm("mov.b64 %0, {%1, %1};" : "=l"(r) : "f"(x)); return r;
}
__device__ __forceinline__ void unpk2(float& lo, float& hi, ull v) {
    asm("mov.b64 {%0, %1}, %2;" : "=f"(lo), "=f"(hi) : "l"(v));
}

// ---------------- tf32 / mma / ldmatrix helpers (cross) ----------------
__device__ __forceinline__ uint tf32r(float x) {
    uint u; asm("cvt.rna.tf32.f32 %0, %1;" : "=r"(u) : "f"(x)); return u;
}
__device__ __forceinline__ void mma_tf32(float* d, uint a0, uint a1, uint a2, uint a3,
                                         uint b0, uint b1) {
    asm volatile(
        "mma.sync.aligned.m16n8k8.row.col.f32.tf32.tf32.f32 "
        "{%0,%1,%2,%3}, {%4,%5,%6,%7}, {%8,%9}, {%0,%1,%2,%3};"
        : "+f"(d[0]), "+f"(d[1]), "+f"(d[2]), "+f"(d[3])
        : "r"(a0), "r"(a1), "r"(a2), "r"(a3), "r"(b0), "r"(b1));
}
__device__ __forceinline__ void ldsm_x4(uint& r0, uint& r1, uint& r2, uint& r3, uint a) {
    asm volatile("ldmatrix.sync.aligned.m8n8.x4.shared.b16 {%0,%1,%2,%3}, [%4];"
        : "=r"(r0), "=r"(r1), "=r"(r2), "=r"(r3) : "r"(a));
}

// ================= fused KNN (z=0,1; 2 queries/warp) + 4-way transform (z=2, 32 pts) =================
#define TILE 2048   // 32KB tile -> 4 blocks/SM

__global__ __launch_bounds__(512, 4) void knn_transform_kernel(
    const float* __restrict__ pc1, const float* __restrict__ pc2,
    int* __restrict__ i12, int* __restrict__ i21,
    const float* __restrict__ f1g, const float* __restrict__ f2g,
    const float* __restrict__ w11, const float* __restrict__ b11,
    const float* __restrict__ w22, const float* __restrict__ b22,
    float* __restrict__ q1o, float* __restrict__ q2o,
    float* __restrict__ r1o, float* __restrict__ r2o)
{
    extern __shared__ char smraw[];
    const int tid = threadIdx.x;

    if (blockIdx.z == 2) {
        // ---- 4-way feature transform: 32 points per block, weights loaded once ----
        ull* s_wp  = (ull*)smraw;       // 4096: [c][m] = (w11[m][c], w22[m][c])
        ull* s_f12 = s_wp + 4096;       // 1024: [c][np] = (f1, f2)
        ull* s_f21 = s_f12 + 1024;      // 1024: [c][np] = (f2, f1)
        const int b = blockIdx.y;
        for (int i = tid; i < 4096; i += 512) {
            int m = i >> 6, c = i & 63;
            s_wp[c * 64 + m] = pk2(w11[i], w22[i]);
        }
        const int m = tid & 63, grp = tid >> 6;
        const int np = grp * 2;
        ull bq;
        {
            // compute after weights present is fine (register only)
            bq = pk2(b11[m], b22[m]);
        }
        #pragma unroll
        for (int half = 0; half < 2; half++) {
            const int n0 = blockIdx.x * 32 + half * 16;
            __syncthreads();
            for (int i = tid; i < 1024; i += 512) {
                int c = i >> 4, npp = i & 15;
                float a = f1g[(b * 64 + c) * N + n0 + npp];
                float d = f2g[(b * 64 + c) * N + n0 + npp];
                s_f12[i] = pk2(a, d);
                s_f21[i] = pk2(d, a);
            }
            __syncthreads();
            ull a0 = bq, a1 = bq, r0 = bq, r1v = bq;
            #pragma unroll 8
            for (int c = 0; c < 64; c++) {
                ull wv = s_wp[c * 64 + m];
                a0  = ffma2(s_f12[c * 16 + np],     wv, a0);
                a1  = ffma2(s_f12[c * 16 + np + 1], wv, a1);
                r0  = ffma2(s_f21[c * 16 + np],     wv, r0);
                r1v = ffma2(s_f21[c * 16 + np + 1], wv, r1v);
            }
            float v1, v2;
            int q = (b * N + n0 + np) * 64 + m;
            unpk2(v1, v2, a0);  q1o[q] = v1;      q2o[q] = v2;
            unpk2(v1, v2, a1);  q1o[q + 64] = v1; q2o[q + 64] = v2;
            unpk2(v1, v2, r0);  r1o[q] = v1;      r2o[q] = v2;
            unpk2(v1, v2, r1v); r1o[q + 64] = v1; r2o[q + 64] = v2;
        }
        return;
    }

    // ---- KNN: 2 queries per warp, top-16 list per 16-lane half (256 blocks exactly) ----
    ulonglong2* s_t0 = (ulonglong2*)smraw;
    ulonglong2* s_t1 = s_t0 + (TILE / 2);
    const int dir = blockIdx.z;
    const float* q  = dir ? pc2 : pc1;
    const float* db = dir ? pc1 : pc2;
    int* oi = dir ? i21 : i12;
    const int b = blockIdx.y;
    const int warp = tid >> 5, lane = tid & 31;
    const int nA = blockIdx.x * 32 + warp * 2;
    const int nB = nA + 1;
    const float* qb = q + b * 3 * N;
    const ull m2qAx = dup2(-2.0f * qb[nA]);
    const ull m2qAy = dup2(-2.0f * qb[N + nA]);
    const ull m2qAz = dup2(-2.0f * qb[2 * N + nA]);
    const ull m2qBx = dup2(-2.0f * qb[nB]);
    const ull m2qBy = dup2(-2.0f * qb[N + nB]);
    const ull m2qBz = dup2(-2.0f * qb[2 * N + nB]);
    const float* dbb = db + b * 3 * N;

    float bd = 3.0e38f;
    int bi = 0;
    float tauA = 3.0e38f, tauB = 3.0e38f;
    const bool halfA = (lane < 16);

    for (int t = 0; t < N; t += TILE) {
        __syncthreads();
        const float2* gx = (const float2*)(dbb + t);
        const float2* gy = (const float2*)(dbb + N + t);
        const float2* gz = (const float2*)(dbb + 2 * N + t);
        for (int i = tid; i < TILE / 2; i += 512) {
            float2 x = gx[i], y = gy[i], z = gz[i];
            float w0 = x.x * x.x + y.x * y.x + z.x * z.x;
            float w1 = x.y * x.y + y.y * y.y + z.y * z.y;
            ulonglong2 A, B;
            A.x = *(const ull*)&x; A.y = *(const ull*)&y;
            B.x = *(const ull*)&z; B.y = pk2(w0, w1);
            s_t0[i] = A; s_t1[i] = B;
        }
        __syncthreads();
        for (int p = 0; p < TILE / 2; p += 32) {
            ulonglong2 t0 = s_t0[p + lane];
            ulonglong2 t1 = s_t1[p + lane];
            ull dA = ffma2(t0.x, m2qAx, t1.y);
            dA = ffma2(t0.y, m2qAy, dA);
            dA = ffma2(t1.x, m2qAz, dA);
            ull dB = ffma2(t0.x, m2qBx, t1.y);
            dB = ffma2(t0.y, m2qBy, dB);
            dB = ffma2(t1.x, m2qBz, dB);
            float dA0, dA1, dB0, dB1;
            unpk2(dA0, dA1, dA);
            unpk2(dB0, dB1, dB);
            bool hit = (fminf(dA0, dA1) < tauA) | (fminf(dB0, dB1) < tauB);
            if (__ballot_sync(FULLMASK, hit)) {
                const int base = t + 2 * p;
                unsigned mA0 = __ballot_sync(FULLMASK, dA0 < tauA);
                unsigned mA1 = __ballot_sync(FULLMASK, dA1 < tauA);
                unsigned mB0 = __ballot_sync(FULLMASK, dB0 < tauB);
                unsigned mB1 = __ballot_sync(FULLMASK, dB1 < tauB);
                unsigned mm0 = halfA ? mA0 : mB0;
                unsigned mm1 = halfA ? mA1 : mB1;
                int n0it = max(__popc(mA0), __popc(mB0));
                for (int it = 0; it < n0it; it++) {
                    int src = __ffs(mm0) - 1;
                    float vA = __shfl_sync(FULLMASK, dA0, src & 31);
                    float vB = __shfl_sync(FULLMASK, dB0, src & 31);
                    float dd = halfA ? vA : vB;
                    float up  = __shfl_up_sync(FULLMASK, bd, 1, 16);
                    int   upi = __shfl_up_sync(FULLMASK, bi, 1, 16);
                    if ((lane & 15) == 0) up = -3.0e38f;
                    if (mm0 && bd > dd) {
                        bool tk = up > dd;
                        bd = tk ? up : dd;
                        bi = tk ? upi : base + 2 * src;
                    }
                    mm0 &= mm0 - 1;
                }
                int n1it = max(__popc(mA1), __popc(mB1));
                for (int it = 0; it < n1it; it++) {
                    int src = __ffs(mm1) - 1;
                    float vA = __shfl_sync(FULLMASK, dA1, src & 31);
                    float vB = __shfl_sync(FULLMASK, dB1, src & 31);
                    float dd = halfA ? vA : vB;
                    float up  = __shfl_up_sync(FULLMASK, bd, 1, 16);
                    int   upi = __shfl_up_sync(FULLMASK, bi, 1, 16);
                    if ((lane & 15) == 0) up = -3.0e38f;
                    if (mm1 && bd > dd) {
                        bool tk = up > dd;
                        bd = tk ? up : dd;
                        bi = tk ? upi : base + 2 * src + 1;
                    }
                    mm1 &= mm1 - 1;
                }
                tauA = __shfl_sync(FULLMASK, bd, 15);
                tauB = __shfl_sync(FULLMASK, bd, 31);
            }
        }
    }
    const int nOut = halfA ? nA : nB;
    oi[((b * N) + nOut) * 16 + (lane & 15)] = bi;
}

// ================= tf32 tensor-core cross (+ optional fp32 final-linear epilogue) =================
// block = 256 threads = 8 warps; each warp: 4 queries, m16n8k8 tf32 MMA per query.
// smem (uint words):
#define U_W1 0          // 64*68
#define U_W2 4352       // 64*68
#define U_W3 8704       // 64*68 (fp32, epilogue)
#define U_PWT 13056     // 192
#define U_PB  13248     // 64
#define U_B1  13312     // 64
#define U_B2  13376     // 64
#define U_B3  13440     // 64
#define U_H   13504     // 8 warps * 16*68 = 8704
#define U_POOL 22208    // 8 warps * 256 = 2048
#define U_D   24256     // 8 warps * 16 float4 = 512
#define SMEM_WORDS 24768

template <int NL, int EPI>
__global__ __launch_bounds__(256) void cross_kernel(
    const int* __restrict__ iA, const int* __restrict__ iB,
    const float* __restrict__ xA, const float* __restrict__ xB,
    const float* __restrict__ p1A, const float* __restrict__ p2A,
    const float* __restrict__ p1B, const float* __restrict__ p2B,
    const float* __restrict__ posw, const float* __restrict__ posb,
    const float* __restrict__ w1, const float* __restrict__ b1,
    const float* __restrict__ w2, const float* __restrict__ b2,
    const float* __restrict__ w3A, const float* __restrict__ b3A,
    const float* __restrict__ w3B, const float* __restrict__ b3B,
    float* __restrict__ obnA, float* __restrict__ obnB,
    float* __restrict__ ocnA, float* __restrict__ ocnB)
{
    extern __shared__ uint smu[];
    uint*  s_w1u = smu + U_W1;
    uint*  s_w2u = smu + U_W2;
    float* s_w3  = (float*)(smu + U_W3);
    float* s_pwt = (float*)(smu + U_PWT);
    float* s_pb  = (float*)(smu + U_PB);
    float* s_b1  = (float*)(smu + U_B1);
    float* s_b2  = (float*)(smu + U_B2);
    float* s_b3  = (float*)(smu + U_B3);
    uint*  s_hall = smu + U_H;
    float* s_pool = (float*)(smu + U_POOL);
    float4* s_dall = (float4*)(smu + U_D);

    const int dir = blockIdx.y;
    const int* idx = dir ? iB : iA;
    const float* xyz1 = dir ? xB : xA;
    const float* xyz2 = dir ? xA : xB;
    const float* p1 = dir ? p1B : p1A;
    const float* p2 = dir ? p2B : p2A;
    const float* w3 = dir ? w3B : w3A;
    const float* b3 = dir ? b3B : b3A;
    float* obn = dir ? obnB : obnA;
    float* ocn = dir ? ocnB : ocnA;

    const int tid = threadIdx.x;
    for (int i = tid; i < 4096; i += 256) {
        int m = i >> 6, c = i & 63;
        s_w1u[m * 68 + c] = tf32r(w1[i]);
        if (NL == 2) s_w2u[m * 68 + c] = tf32r(w2[i]);
        if (EPI)     s_w3[m * 68 + c] = w3[i];
    }
    if (tid < 192) s_pwt[tid] = posw[(tid & 63) * 3 + (tid >> 6)];
    if (tid < 64) {
        s_pb[tid] = posb[tid];
        s_b1[tid] = b1[tid];
        if (NL == 2) s_b2[tid] = b2[tid];
        if (EPI)     s_b3[tid] = b3[tid];
    }
    __syncthreads();

    const int warp = tid >> 5, lane = tid & 31;
    const int g = lane >> 2, t = lane & 3;
    uint*   s_h  = s_hall + warp * 1088;   // 16 rows * 68
    float*  s_pw = s_pool + warp * 256;    // 4 queries * 64
    float4* s_d  = s_dall + warp * 16;     // 16 neighbor rows (dx,dy,dz,j)
    const int wq0 = (blockIdx.x * 8 + warp) * 4;

    // ldmatrix per-lane bases
    const int r8 = lane & 7, q8 = lane >> 3;
    const int rowA = r8 + ((q8 >> 1) << 3);
    const int cofA = (q8 & 1) * 4;
    const uint aAddr = (uint)__cvta_generic_to_shared(s_h + rowA * 68 + cofA);
    const int rB4 = ((q8 >> 1) << 3) + r8;
    const int cofB = (q8 & 1) * 4;
    const uint b1Addr = (uint)__cvta_generic_to_shared(s_w1u + rB4 * 68 + cofB);
    const uint b2Addr = (uint)__cvta_generic_to_shared(s_w2u + rB4 * 68 + cofB);

    const float pw0a = s_pwt[lane],      pw1a = s_pwt[64 + lane],  pw2a = s_pwt[128 + lane];
    const float pw0b = s_pwt[lane + 32], pw1b = s_pwt[96 + lane],  pw2b = s_pwt[160 + lane];
    const float pba = s_pb[lane], pbb = s_pb[lane + 32];

    for (int qi = 0; qi < 4; qi++) {
        const int q = wq0 + qi;
        const int b = q >> 13, n = q & (N - 1);
        const int myidx = idx[q * 16 + (lane & 15)];
        const float p1a = p1[q * 64 + lane];
        const float p1b = p1[q * 64 + 32 + lane];
        const float* x1b = xyz1 + b * 3 * N;
        const float qx = x1b[n], qy = x1b[N + n], qz = x1b[2 * N + n];
        const float* x2b = xyz2 + b * 3 * N;

        // lanes 0-15 publish their neighbor's (dx,dy,dz,j) row
        if (lane < 16) {
            float nx = x2b[myidx], ny = x2b[N + myidx], nz = x2b[2 * N + myidx];
            s_d[lane] = make_float4(nx - qx, ny - qy, nz - qz, __int_as_float(myidx));
        }
        __syncwarp();

        // gather: h[k][c] = leaky(g2 + p1 + posf), tf32-rounded
        #pragma unroll
        for (int k = 0; k < 16; k++) {
            float4 dv = s_d[k];
            int j = __float_as_int(dv.w);
            const float* p2r = p2 + ((size_t)((b << 13) + j)) * 64;
            float ga = p2r[lane], gb = p2r[lane + 32];
            float pa = pba + dv.x * pw0a + dv.y * pw1a + dv.z * pw2a;
            float pb = pbb + dv.x * pw0b + dv.y * pw1b + dv.z * pw2b;
            s_h[k * 68 + lane]      = tf32r(leaky(ga + p1a + pa));
            s_h[k * 68 + 32 + lane] = tf32r(leaky(gb + p1b + pb));
        }
        __syncwarp();

        float d[8][4];
        // ----- layer 1 (bias in accumulator) -----
        #pragma unroll
        for (int nt = 0; nt < 8; nt++) {
            float2 bv = *(const float2*)&s_b1[nt * 8 + t * 2];
            d[nt][0] = bv.x; d[nt][1] = bv.y; d[nt][2] = bv.x; d[nt][3] = bv.y;
        }
        #pragma unroll
        for (int ks = 0; ks < 8; ks++) {
            uint f0, f1, f2, f3;                 // = a0, a2, a1, a3
            ldsm_x4(f0, f1, f2, f3, aAddr + ks * 32);
            #pragma unroll
            for (int nj = 0; nj < 4; nj++) {
                uint b0, b1v, b2v, b3v;          // (b0,b1) for nt=2nj, (b2,b3) for nt=2nj+1
                ldsm_x4(b0, b1v, b2v, b3v, b1Addr + (nj * 16 * 68 + ks * 8) * 4);
                mma_tf32(d[2 * nj],     f0, f2, f1, f3, b0, b1v);
                mma_tf32(d[2 * nj + 1], f0, f2, f1, f3, b2v, b3v);
            }
        }

        if (NL == 2) {
            __syncwarp();
            #pragma unroll
            for (int nt = 0; nt < 8; nt++) {
                int c0 = nt * 8 + t * 2;
                s_h[g * 68 + c0]           = tf32r(leaky(d[nt][0]));
                s_h[g * 68 + c0 + 1]       = tf32r(leaky(d[nt][1]));
                s_h[(g + 8) * 68 + c0]     = tf32r(leaky(d[nt][2]));
                s_h[(g + 8) * 68 + c0 + 1] = tf32r(leaky(d[nt][3]));
            }
            __syncwarp();
            #pragma unroll
            for (int nt = 0; nt < 8; nt++) {
                float2 bv = *(const float2*)&s_b2[nt * 8 + t * 2];
                d[nt][0] = bv.x; d[nt][1] = bv.y; d[nt][2] = bv.x; d[nt][3] = bv.y;
            }
            #pragma unroll
            for (int ks = 0; ks < 8; ks++) {
                uint f0, f1, f2, f3;
                ldsm_x4(f0, f1, f2, f3, aAddr + ks * 32);
                #pragma unroll
                for (int nj = 0; nj < 4; nj++) {
                    uint b0, b1v, b2v, b3v;
                    ldsm_x4(b0, b1v, b2v, b3v, b2Addr + (nj * 16 * 68 + ks * 8) * 4);
                    mma_tf32(d[2 * nj],     f0, f2, f1, f3, b0, b1v);
                    mma_tf32(d[2 * nj + 1], f0, f2, f1, f3, b2v, b3v);
                }
            }
        }

        // maxpool over the 16 rows (k), then leaky (monotonic)
        #pragma unroll
        for (int nt = 0; nt < 8; nt++) {
            float u0 = fmaxf(d[nt][0], d[nt][2]);
            float u1 = fmaxf(d[nt][1], d[nt][3]);
            u0 = fmaxf(u0, __shfl_xor_sync(FULLMASK, u0, 4));
            u1 = fmaxf(u1, __shfl_xor_sync(FULLMASK, u1, 4));
            u0 = fmaxf(u0, __shfl_xor_sync(FULLMASK, u0, 8));
            u1 = fmaxf(u1, __shfl_xor_sync(FULLMASK, u1, 8));
            u0 = fmaxf(u0, __shfl_xor_sync(FULLMASK, u0, 16));
            u1 = fmaxf(u1, __shfl_xor_sync(FULLMASK, u1, 16));
            if (nt == g) {
                if (EPI) {
                    s_pw[qi * 64 + g * 8 + t * 2]     = leaky(u0);
                    s_pw[qi * 64 + g * 8 + t * 2 + 1] = leaky(u1);
                } else {
                    ocn[((b * 64) + g * 8 + t * 2) * N + n]     = leaky(u0);
                    ocn[((b * 64) + g * 8 + t * 2 + 1) * N + n] = leaky(u1);
                }
            }
        }
        __syncwarp();
    }

    if (EPI) {
        // fp32 final linear: lane owns channels (lane, lane+32); 4 queries
        float acc[4][2];
        #pragma unroll
        for (int q4 = 0; q4 < 4; q4++) { acc[q4][0] = s_b3[lane]; acc[q4][1] = s_b3[lane + 32]; }
        #pragma unroll
        for (int jb = 0; jb < 16; jb++) {
            float4 wa = *(const float4*)&s_w3[lane * 68 + jb * 4];
            float4 wb = *(const float4*)&s_w3[(lane + 32) * 68 + jb * 4];
            #pragma unroll
            for (int q4 = 0; q4 < 4; q4++) {
                float4 hv = *(const float4*)&s_pw[q4 * 64 + jb * 4];
                acc[q4][0] += hv.x * wa.x + hv.y * wa.y + hv.z * wa.z + hv.w * wa.w;
                acc[q4][1] += hv.x * wb.x + hv.y * wb.y + hv.z * wb.z + hv.w * wb.w;
            }
        }
        #pragma unroll
        for (int q4 = 0; q4 < 4; q4++) {
            const int q = wq0 + q4;
            const int b = q >> 13, n = q & (N - 1);
            obn[q * 64 + lane]      = acc[q4][0];
            obn[q * 64 + 32 + lane] = acc[q4][1];
            ocn[((b * 64) + lane) * N + n]      = acc[q4][0];
            ocn[((b * 64) + lane + 32) * N + n] = acc[q4][1];
        }
    }
}

// ---------------- launch ----------------
extern "C" void kernel_launch(void* const* d_in, const int* in_sizes, int n_in,
                              void* d_out, int out_size)
{
    const float* pc1     = (const float*)d_in[0];
    const float* pc2     = (const float*)d_in[1];
    const float* feat1   = (const float*)d_in[2];
    const float* feat2   = (const float*)d_in[3];
    const float* t11_w   = (const float*)d_in[4];
    const float* t11_b   = (const float*)d_in[5];
    const float* t22_w   = (const float*)d_in[6];
    const float* t22_b   = (const float*)d_in[7];
    const float* pos1_w  = (const float*)d_in[8];
    const float* pos1_b  = (const float*)d_in[9];
    const float* mlp1_w1 = (const float*)d_in[10];
    const float* mlp1_b1 = (const float*)d_in[11];
    const float* mlp1_w2 = (const float*)d_in[12];
    const float* mlp1_b2 = (const float*)d_in[13];
    const float* t1_w    = (const float*)d_in[14];
    const float* t1_b    = (const float*)d_in[15];
    const float* t2_w    = (const float*)d_in[16];
    const float* t2_b    = (const float*)d_in[17];
    const float* pos2_w  = (const float*)d_in[18];
    const float* pos2_b  = (const float*)d_in[19];
    const float* mlp2_w1 = (const float*)d_in[20];
    const float* mlp2_b1 = (const float*)d_in[21];
    float* out = (float*)d_out;

    float *q1, *q2, *r1, *r2, *f1, *f2;
    int *i12, *i21;
    cudaGetSymbolAddress((void**)&q1, g_q1);
    cudaGetSymbolAddress((void**)&q2, g_q2);
    cudaGetSymbolAddress((void**)&r1, g_r1);
    cudaGetSymbolAddress((void**)&r2, g_r2);
    cudaGetSymbolAddress((void**)&f1, g_f1);
    cudaGetSymbolAddress((void**)&f2, g_f2);
    cudaGetSymbolAddress((void**)&i12, g_i12);
    cudaGetSymbolAddress((void**)&i21, g_i21);

    // fused KNN (z=0,1; 32KB tiles, 256 blocks each) + transforms (z=2; 48KB, 32 pts/block)
    const size_t smem_kt = 49152;
    cudaFuncSetAttribute(knn_transform_kernel, cudaFuncAttributeMaxDynamicSharedMemorySize, (int)smem_kt);
    knn_transform_kernel<<<dim3(N / 32, BB, 3), 512, smem_kt>>>(
        pc1, pc2, i12, i21,
        feat1, feat2, t11_w, t11_b, t22_w, t22_b,
        q1, q2, r1, r2);

    const size_t smem = (size_t)SMEM_WORDS * 4;
    cudaFuncSetAttribute(cross_kernel<2,1>, cudaFuncAttributeMaxDynamicSharedMemorySize, (int)smem);
    cudaFuncSetAttribute(cross_kernel<1,0>, cudaFuncAttributeMaxDynamicSharedMemorySize, (int)smem);

    // cross 1 & 2 fused (grid.y = direction) with fp32 final-linear epilogue
    cross_kernel<2,1><<<dim3(BB * N / 32, 2), 256, smem>>>(
        i12, i21, pc1, pc2,
        q1, q2, r1, r2,
        pos1_w, pos1_b, mlp1_w1, mlp1_b1, mlp1_w2, mlp1_b2,
        t1_w, t1_b, t2_w, t2_b,
        f1, f2, out, out + (size_t)BB * 64 * N);

    // cross 3 (1 mlp layer), transposed direct write to output region 2
    cross_kernel<1,0><<<dim3(BB * N / 32, 1), 256, smem>>>(
        i12, i12, pc1, pc2,
        f1, f2, f1, f2,
        pos2_w, pos2_b, mlp2_w1, mlp2_b1, mlp2_w1, mlp2_b1,
        mlp2_w1, mlp2_b1, mlp2_w1, mlp2_b1,
        out + (size_t)2 * BB * 64 * N, out + (size_t)2 * BB * 64 * N,
        out + (size_t)2 * BB * 64 * N, out + (size_t)2 * BB * 64 * N);
}

// round 15
// speedup vs baseline: 1.1195x; 1.1195x over previous
#include <cuda_runtime.h>

#define N 8192
#define BB 2
#define CH 64
#define KNB 16
#define FULLMASK 0xffffffffu
typedef unsigned long long ull;
typedef unsigned int uint;

// ---------------- scratch (static device globals; no allocation) ----------------
__device__ float g_q1[BB*N*CH];
__device__ float g_q2[BB*N*CH];
__device__ float g_r1[BB*N*CH];
__device__ float g_r2[BB*N*CH];
__device__ float g_f1[BB*N*CH];
__device__ float g_f2[BB*N*CH];
__device__ int   g_i12[BB*N*KNB];
__device__ int   g_i21[BB*N*KNB];

__device__ __forceinline__ float leaky(float x) { return fmaxf(x, 0.1f * x); }

// ---------------- packed f32x2 helpers ----------------
__device__ __forceinline__ ull ffma2(ull a, ull b, ull c) {
    ull d; asm("fma.rn.f32x2 %0, %1, %2, %3;" : "=l"(d) : "l"(a), "l"(b), "l"(c)); return d;
}
__device__ __forceinline__ ull pk2(float x, float y) {
    ull r; asm("mov.b64 %0, {%1, %2};" : "=l"(r) : "f"(x), "f"(y)); return r;
}
__device__ __forceinline__ ull dup2(float x) {
    ull r; asm("mov.b64 %0, {%1, %1};" : "=l"(r) : "f"(x)); return r;
}
__device__ __forceinline__ void unpk2(float& lo, float& hi, ull v) {
    asm("mov.b64 {%0, %1}, %2;" : "=f"(lo), "=f"(hi) : "l"(v));
}

// ---------------- tf32 / mma / ldmatrix helpers (cross) ----------------
__device__ __forceinline__ uint tf32r(float x) {
    uint u; asm("cvt.rna.tf32.f32 %0, %1;" : "=r"(u) : "f"(x)); return u;
}
__device__ __forceinline__ void mma_tf32(float* d, uint a0, uint a1, uint a2, uint a3,
                                         uint b0, uint b1) {
    asm volatile(
        "mma.sync.aligned.m16n8k8.row.col.f32.tf32.tf32.f32 "
        "{%0,%1,%2,%3}, {%4,%5,%6,%7}, {%8,%9}, {%0,%1,%2,%3};"
        : "+f"(d[0]), "+f"(d[1]), "+f"(d[2]), "+f"(d[3])
        : "r"(a0), "r"(a1), "r"(a2), "r"(a3), "r"(b0), "r"(b1));
}
__device__ __forceinline__ void ldsm_x4(uint& r0, uint& r1, uint& r2, uint& r3, uint a) {
    asm volatile("ldmatrix.sync.aligned.m8n8.x4.shared.b16 {%0,%1,%2,%3}, [%4];"
        : "=r"(r0), "=r"(r1), "=r"(r2), "=r"(r3) : "r"(a));
}

// ================= fused KNN (z=0,1; 2 queries/warp) + 4-way transform (z=2) =================
#define TILE 2048   // 32KB tile -> 4 blocks/SM

__global__ __launch_bounds__(512, 4) void knn_transform_kernel(
    const float* __restrict__ pc1, const float* __restrict__ pc2,
    int* __restrict__ i12, int* __restrict__ i21,
    const float* __restrict__ f1g, const float* __restrict__ f2g,
    const float* __restrict__ w11, const float* __restrict__ b11,
    const float* __restrict__ w22, const float* __restrict__ b22,
    float* __restrict__ q1o, float* __restrict__ q2o,
    float* __restrict__ r1o, float* __restrict__ r2o)
{
    extern __shared__ char smraw[];
    const int tid = threadIdx.x;

    if (blockIdx.z == 2) {
        ull* s_wp  = (ull*)smraw;
        ull* s_f12 = s_wp + 4096;
        ull* s_f21 = s_f12 + 1024;
        const int b = blockIdx.y, n0 = blockIdx.x * 16;
        for (int i = tid; i < 4096; i += 512) {
            int m = i >> 6, c = i & 63;
            s_wp[c * 64 + m] = pk2(w11[i], w22[i]);
        }
        for (int i = tid; i < 1024; i += 512) {
            int c = i >> 4, np = i & 15;
            float a = f1g[(b * 64 + c) * N + n0 + np];
            float d = f2g[(b * 64 + c) * N + n0 + np];
            s_f12[i] = pk2(a, d);
            s_f21[i] = pk2(d, a);
        }
        __syncthreads();
        const int m = tid & 63, grp = tid >> 6;
        ull bq = pk2(b11[m], b22[m]);
        ull a0 = bq, a1 = bq, r0 = bq, r1v = bq;
        const int np = grp * 2;
        #pragma unroll 8
        for (int c = 0; c < 64; c++) {
            ull wv = s_wp[c * 64 + m];
            a0  = ffma2(s_f12[c * 16 + np],     wv, a0);
            a1  = ffma2(s_f12[c * 16 + np + 1], wv, a1);
            r0  = ffma2(s_f21[c * 16 + np],     wv, r0);
            r1v = ffma2(s_f21[c * 16 + np + 1], wv, r1v);
        }
        float v1, v2;
        int q = (b * N + n0 + np) * 64 + m;
        unpk2(v1, v2, a0);  q1o[q] = v1;      q2o[q] = v2;
        unpk2(v1, v2, a1);  q1o[q + 64] = v1; q2o[q + 64] = v2;
        unpk2(v1, v2, r0);  r1o[q] = v1;      r2o[q] = v2;
        unpk2(v1, v2, r1v); r1o[q + 64] = v1; r2o[q + 64] = v2;
        return;
    }

    if (blockIdx.x >= N / 32) return;
    ulonglong2* s_t0 = (ulonglong2*)smraw;
    ulonglong2* s_t1 = s_t0 + (TILE / 2);
    const int dir = blockIdx.z;
    const float* q  = dir ? pc2 : pc1;
    const float* db = dir ? pc1 : pc2;
    int* oi = dir ? i21 : i12;
    const int b = blockIdx.y;
    const int warp = tid >> 5, lane = tid & 31;
    const int nA = blockIdx.x * 32 + warp * 2;
    const int nB = nA + 1;
    const float* qb = q + b * 3 * N;
    const ull m2qAx = dup2(-2.0f * qb[nA]);
    const ull m2qAy = dup2(-2.0f * qb[N + nA]);
    const ull m2qAz = dup2(-2.0f * qb[2 * N + nA]);
    const ull m2qBx = dup2(-2.0f * qb[nB]);
    const ull m2qBy = dup2(-2.0f * qb[N + nB]);
    const ull m2qBz = dup2(-2.0f * qb[2 * N + nB]);
    const float* dbb = db + b * 3 * N;

    float bd = 3.0e38f;
    int bi = 0;
    float tauA = 3.0e38f, tauB = 3.0e38f;
    const bool halfA = (lane < 16);

    for (int t = 0; t < N; t += TILE) {
        __syncthreads();
        const float2* gx = (const float2*)(dbb + t);
        const float2* gy = (const float2*)(dbb + N + t);
        const float2* gz = (const float2*)(dbb + 2 * N + t);
        for (int i = tid; i < TILE / 2; i += 512) {
            float2 x = gx[i], y = gy[i], z = gz[i];
            float w0 = x.x * x.x + y.x * y.x + z.x * z.x;
            float w1 = x.y * x.y + y.y * y.y + z.y * z.y;
            ulonglong2 A, B;
            A.x = *(const ull*)&x; A.y = *(const ull*)&y;
            B.x = *(const ull*)&z; B.y = pk2(w0, w1);
            s_t0[i] = A; s_t1[i] = B;
        }
        __syncthreads();
        for (int p = 0; p < TILE / 2; p += 32) {
            ulonglong2 t0 = s_t0[p + lane];
            ulonglong2 t1 = s_t1[p + lane];
            ull dA = ffma2(t0.x, m2qAx, t1.y);
            dA = ffma2(t0.y, m2qAy, dA);
            dA = ffma2(t1.x, m2qAz, dA);
            ull dB = ffma2(t0.x, m2qBx, t1.y);
            dB = ffma2(t0.y, m2qBy, dB);
            dB = ffma2(t1.x, m2qBz, dB);
            float dA0, dA1, dB0, dB1;
            unpk2(dA0, dA1, dA);
            unpk2(dB0, dB1, dB);
            bool hit = (fminf(dA0, dA1) < tauA) | (fminf(dB0, dB1) < tauB);
            if (__ballot_sync(FULLMASK, hit)) {
                const int base = t + 2 * p;
                unsigned mA0 = __ballot_sync(FULLMASK, dA0 < tauA);
                unsigned mA1 = __ballot_sync(FULLMASK, dA1 < tauA);
                unsigned mB0 = __ballot_sync(FULLMASK, dB0 < tauB);
                unsigned mB1 = __ballot_sync(FULLMASK, dB1 < tauB);
                unsigned mm0 = halfA ? mA0 : mB0;
                unsigned mm1 = halfA ? mA1 : mB1;
                int n0it = max(__popc(mA0), __popc(mB0));
                for (int it = 0; it < n0it; it++) {
                    int src = __ffs(mm0) - 1;
                    float vA = __shfl_sync(FULLMASK, dA0, src & 31);
                    float vB = __shfl_sync(FULLMASK, dB0, src & 31);
                    float dd = halfA ? vA : vB;
                    float up  = __shfl_up_sync(FULLMASK, bd, 1, 16);
                    int   upi = __shfl_up_sync(FULLMASK, bi, 1, 16);
                    if ((lane & 15) == 0) up = -3.0e38f;
                    if (mm0 && bd > dd) {
                        bool tk = up > dd;
                        bd = tk ? up : dd;
                        bi = tk ? upi : base + 2 * src;
                    }
                    mm0 &= mm0 - 1;
                }
                int n1it = max(__popc(mA1), __popc(mB1));
                for (int it = 0; it < n1it; it++) {
                    int src = __ffs(mm1) - 1;
                    float vA = __shfl_sync(FULLMASK, dA1, src & 31);
                    float vB = __shfl_sync(FULLMASK, dB1, src & 31);
                    float dd = halfA ? vA : vB;
                    float up  = __shfl_up_sync(FULLMASK, bd, 1, 16);
                    int   upi = __shfl_up_sync(FULLMASK, bi, 1, 16);
                    if ((lane & 15) == 0) up = -3.0e38f;
                    if (mm1 && bd > dd) {
                        bool tk = up > dd;
                        bd = tk ? up : dd;
                        bi = tk ? upi : base + 2 * src + 1;
                    }
                    mm1 &= mm1 - 1;
                }
                tauA = __shfl_sync(FULLMASK, bd, 15);
                tauB = __shfl_sync(FULLMASK, bd, 31);
            }
        }
    }
    const int nOut = halfA ? nA : nB;
    oi[((b * N) + nOut) * 16 + (lane & 15)] = bi;
}

// ================= tf32 tensor-core cross (+ optional fp32 final-linear epilogue) =================
// block = 256 threads = 8 warps; each warp: 4 queries, m16n8k8 tf32 MMA per query.
// smem (uint words):
#define U_W1 0          // 64*68
#define U_W2 4352       // 64*68
#define U_W3 8704       // 64*68 (fp32, epilogue)
#define U_PWT 13056     // 192
#define U_PB  13248     // 64
#define U_B1  13312     // 64
#define U_B2  13376     // 64
#define U_B3  13440     // 64
#define U_H   13504     // 8 warps * 16*68 = 8704
#define U_POOL 22208    // 8 warps * 256 = 2048
#define SMEM_WORDS 24256

template <int NL, int EPI>
__global__ __launch_bounds__(256) void cross_kernel(
    const int* __restrict__ iA, const int* __restrict__ iB,
    const float* __restrict__ xA, const float* __restrict__ xB,
    const float* __restrict__ p1A, const float* __restrict__ p2A,
    const float* __restrict__ p1B, const float* __restrict__ p2B,
    const float* __restrict__ posw, const float* __restrict__ posb,
    const float* __restrict__ w1, const float* __restrict__ b1,
    const float* __restrict__ w2, const float* __restrict__ b2,
    const float* __restrict__ w3A, const float* __restrict__ b3A,
    const float* __restrict__ w3B, const float* __restrict__ b3B,
    float* __restrict__ obnA, float* __restrict__ obnB,
    float* __restrict__ ocnA, float* __restrict__ ocnB)
{
    extern __shared__ uint smu[];
    uint*  s_w1u = smu + U_W1;
    uint*  s_w2u = smu + U_W2;
    float* s_w3  = (float*)(smu + U_W3);
    float* s_pwt = (float*)(smu + U_PWT);
    float* s_pb  = (float*)(smu + U_PB);
    float* s_b1  = (float*)(smu + U_B1);
    float* s_b2  = (float*)(smu + U_B2);
    float* s_b3  = (float*)(smu + U_B3);
    uint*  s_hall = smu + U_H;
    float* s_pool = (float*)(smu + U_POOL);

    const int dir = blockIdx.y;
    const int* idx = dir ? iB : iA;
    const float* xyz1 = dir ? xB : xA;
    const float* xyz2 = dir ? xA : xB;
    const float* p1 = dir ? p1B : p1A;
    const float* p2 = dir ? p2B : p2A;
    const float* w3 = dir ? w3B : w3A;
    const float* b3 = dir ? b3B : b3A;
    float* obn = dir ? obnB : obnA;
    float* ocn = dir ? ocnB : ocnA;

    const int tid = threadIdx.x;
    for (int i = tid; i < 4096; i += 256) {
        int m = i >> 6, c = i & 63;
        s_w1u[m * 68 + c] = tf32r(w1[i]);
        if (NL == 2) s_w2u[m * 68 + c] = tf32r(w2[i]);
        if (EPI)     s_w3[m * 68 + c] = w3[i];
    }
    if (tid < 192) s_pwt[tid] = posw[(tid & 63) * 3 + (tid >> 6)];
    if (tid < 64) {
        s_pb[tid] = posb[tid];
        s_b1[tid] = b1[tid];
        if (NL == 2) s_b2[tid] = b2[tid];
        if (EPI)     s_b3[tid] = b3[tid];
    }
    __syncthreads();

    const int warp = tid >> 5, lane = tid & 31;
    const int g = lane >> 2, t = lane & 3;
    uint*  s_h  = s_hall + warp * 1088;   // 16 rows * 68
    float* s_pw = s_pool + warp * 256;    // 4 queries * 64
    const int wq0 = (blockIdx.x * 8 + warp) * 4;

    // ldmatrix per-lane bases
    const int r8 = lane & 7, q8 = lane >> 3;
    const int rowA = r8 + ((q8 >> 1) << 3);
    const int cofA = (q8 & 1) * 4;
    const uint aAddr = (uint)__cvta_generic_to_shared(s_h + rowA * 68 + cofA);
    // B x4: lane groups 0,1 -> rows of nt=2j (cols 0/4); groups 2,3 -> rows of nt=2j+1
    const int rB4 = ((q8 >> 1) << 3) + r8;
    const int cofB = (q8 & 1) * 4;
    const uint b1Addr = (uint)__cvta_generic_to_shared(s_w1u + rB4 * 68 + cofB);
    const uint b2Addr = (uint)__cvta_generic_to_shared(s_w2u + rB4 * 68 + cofB);

    const float pw0a = s_pwt[lane],      pw1a = s_pwt[64 + lane],  pw2a = s_pwt[128 + lane];
    const float pw0b = s_pwt[lane + 32], pw1b = s_pwt[96 + lane],  pw2b = s_pwt[160 + lane];
    const float pba = s_pb[lane], pbb = s_pb[lane + 32];

    for (int qi = 0; qi < 4; qi++) {
        const int q = wq0 + qi;
        const int b = q >> 13, n = q & (N - 1);
        const int myidx = idx[q * 16 + (lane & 15)];
        const float p1a = p1[q * 64 + lane];
        const float p1b = p1[q * 64 + 32 + lane];
        const float* x1b = xyz1 + b * 3 * N;
        const float qx = x1b[n], qy = x1b[N + n], qz = x1b[2 * N + n];
        const float* x2b = xyz2 + b * 3 * N;
        const float nx = x2b[myidx], ny = x2b[N + myidx], nz = x2b[2 * N + myidx];

        // gather: h[k][c] = leaky(g2 + p1 + posf), tf32-rounded
        #pragma unroll
        for (int k = 0; k < 16; k++) {
            int j = __shfl_sync(FULLMASK, myidx, k);
            float dx = __shfl_sync(FULLMASK, nx, k) - qx;
            float dy = __shfl_sync(FULLMASK, ny, k) - qy;
            float dz = __shfl_sync(FULLMASK, nz, k) - qz;
            const float* p2r = p2 + ((size_t)((b << 13) + j)) * 64;
            float ga = p2r[lane], gb = p2r[lane + 32];
            float pa = pba + dx * pw0a + dy * pw1a + dz * pw2a;
            float pb = pbb + dx * pw0b + dy * pw1b + dz * pw2b;
            s_h[k * 68 + lane]      = tf32r(leaky(ga + p1a + pa));
            s_h[k * 68 + 32 + lane] = tf32r(leaky(gb + p1b + pb));
        }
        __syncwarp();

        float d[8][4];
        // ----- layer 1 (bias in accumulator) -----
        #pragma unroll
        for (int nt = 0; nt < 8; nt++) {
            float2 bv = *(const float2*)&s_b1[nt * 8 + t * 2];
            d[nt][0] = bv.x; d[nt][1] = bv.y; d[nt][2] = bv.x; d[nt][3] = bv.y;
        }
        #pragma unroll
        for (int ks = 0; ks < 8; ks++) {
            uint f0, f1, f2, f3;                 // = a0, a2, a1, a3
            ldsm_x4(f0, f1, f2, f3, aAddr + ks * 32);
            #pragma unroll
            for (int nj = 0; nj < 4; nj++) {
                uint b0, b1v, b2v, b3v;          // (b0,b1) for nt=2nj, (b2,b3) for nt=2nj+1
                ldsm_x4(b0, b1v, b2v, b3v, b1Addr + (nj * 16 * 68 + ks * 8) * 4);
                mma_tf32(d[2 * nj],     f0, f2, f1, f3, b0, b1v);
                mma_tf32(d[2 * nj + 1], f0, f2, f1, f3, b2v, b3v);
            }
        }

        if (NL == 2) {
            __syncwarp();
            #pragma unroll
            for (int nt = 0; nt < 8; nt++) {
                int c0 = nt * 8 + t * 2;
                s_h[g * 68 + c0]           = tf32r(leaky(d[nt][0]));
                s_h[g * 68 + c0 + 1]       = tf32r(leaky(d[nt][1]));
                s_h[(g + 8) * 68 + c0]     = tf32r(leaky(d[nt][2]));
                s_h[(g + 8) * 68 + c0 + 1] = tf32r(leaky(d[nt][3]));
            }
            __syncwarp();
            #pragma unroll
            for (int nt = 0; nt < 8; nt++) {
                float2 bv = *(const float2*)&s_b2[nt * 8 + t * 2];
                d[nt][0] = bv.x; d[nt][1] = bv.y; d[nt][2] = bv.x; d[nt][3] = bv.y;
            }
            #pragma unroll
            for (int ks = 0; ks < 8; ks++) {
                uint f0, f1, f2, f3;
                ldsm_x4(f0, f1, f2, f3, aAddr + ks * 32);
                #pragma unroll
                for (int nj = 0; nj < 4; nj++) {
                    uint b0, b1v, b2v, b3v;
                    ldsm_x4(b0, b1v, b2v, b3v, b2Addr + (nj * 16 * 68 + ks * 8) * 4);
                    mma_tf32(d[2 * nj],     f0, f2, f1, f3, b0, b1v);
                    mma_tf32(d[2 * nj + 1], f0, f2, f1, f3, b2v, b3v);
                }
            }
        }

        // maxpool over the 16 rows (k), then leaky (monotonic)
        #pragma unroll
        for (int nt = 0; nt < 8; nt++) {
            float u0 = fmaxf(d[nt][0], d[nt][2]);
            float u1 = fmaxf(d[nt][1], d[nt][3]);
            u0 = fmaxf(u0, __shfl_xor_sync(FULLMASK, u0, 4));
            u1 = fmaxf(u1, __shfl_xor_sync(FULLMASK, u1, 4));
            u0 = fmaxf(u0, __shfl_xor_sync(FULLMASK, u0, 8));
            u1 = fmaxf(u1, __shfl_xor_sync(FULLMASK, u1, 8));
            u0 = fmaxf(u0, __shfl_xor_sync(FULLMASK, u0, 16));
            u1 = fmaxf(u1, __shfl_xor_sync(FULLMASK, u1, 16));
            if (nt == g) {
                if (EPI) {
                    s_pw[qi * 64 + g * 8 + t * 2]     = leaky(u0);
                    s_pw[qi * 64 + g * 8 + t * 2 + 1] = leaky(u1);
                } else {
                    ocn[((b * 64) + g * 8 + t * 2) * N + n]     = leaky(u0);
                    ocn[((b * 64) + g * 8 + t * 2 + 1) * N + n] = leaky(u1);
                }
            }
        }
        __syncwarp();
    }

    if (EPI) {
        // fp32 final linear: lane owns channels (lane, lane+32); 4 queries
        float acc[4][2];
        #pragma unroll
        for (int q4 = 0; q4 < 4; q4++) { acc[q4][0] = s_b3[lane]; acc[q4][1] = s_b3[lane + 32]; }
        #pragma unroll
        for (int jb = 0; jb < 16; jb++) {
            float4 wa = *(const float4*)&s_w3[lane * 68 + jb * 4];
            float4 wb = *(const float4*)&s_w3[(lane + 32) * 68 + jb * 4];
            #pragma unroll
            for (int q4 = 0; q4 < 4; q4++) {
                float4 hv = *(const float4*)&s_pw[q4 * 64 + jb * 4];
                acc[q4][0] += hv.x * wa.x + hv.y * wa.y + hv.z * wa.z + hv.w * wa.w;
                acc[q4][1] += hv.x * wb.x + hv.y * wb.y + hv.z * wb.z + hv.w * wb.w;
            }
        }
        #pragma unroll
        for (int q4 = 0; q4 < 4; q4++) {
            const int q = wq0 + q4;
            const int b = q >> 13, n = q & (N - 1);
            obn[q * 64 + lane]      = acc[q4][0];
            obn[q * 64 + 32 + lane] = acc[q4][1];
            ocn[((b * 64) + lane) * N + n]      = acc[q4][0];
            ocn[((b * 64) + lane + 32) * N + n] = acc[q4][1];
        }
    }
}

// ---------------- launch ----------------
extern "C" void kernel_launch(void* const* d_in, const int* in_sizes, int n_in,
                              void* d_out, int out_size)
{
    const float* pc1     = (const float*)d_in[0];
    const float* pc2     = (const float*)d_in[1];
    const float* feat1   = (const float*)d_in[2];
    const float* feat2   = (const float*)d_in[3];
    const float* t11_w   = (const float*)d_in[4];
    const float* t11_b   = (const float*)d_in[5];
    const float* t22_w   = (const float*)d_in[6];
    const float* t22_b   = (const float*)d_in[7];
    const float* pos1_w  = (const float*)d_in[8];
    const float* pos1_b  = (const float*)d_in[9];
    const float* mlp1_w1 = (const float*)d_in[10];
    const float* mlp1_b1 = (const float*)d_in[11];
    const float* mlp1_w2 = (const float*)d_in[12];
    const float* mlp1_b2 = (const float*)d_in[13];
    const float* t1_w    = (const float*)d_in[14];
    const float* t1_b    = (const float*)d_in[15];
    const float* t2_w    = (const float*)d_in[16];
    const float* t2_b    = (const float*)d_in[17];
    const float* pos2_w  = (const float*)d_in[18];
    const float* pos2_b  = (const float*)d_in[19];
    const float* mlp2_w1 = (const float*)d_in[20];
    const float* mlp2_b1 = (const float*)d_in[21];
    float* out = (float*)d_out;

    float *q1, *q2, *r1, *r2, *f1, *f2;
    int *i12, *i21;
    cudaGetSymbolAddress((void**)&q1, g_q1);
    cudaGetSymbolAddress((void**)&q2, g_q2);
    cudaGetSymbolAddress((void**)&r1, g_r1);
    cudaGetSymbolAddress((void**)&r2, g_r2);
    cudaGetSymbolAddress((void**)&f1, g_f1);
    cudaGetSymbolAddress((void**)&f2, g_f2);
    cudaGetSymbolAddress((void**)&i12, g_i12);
    cudaGetSymbolAddress((void**)&i21, g_i21);

    // fused KNN (z=0,1; 32KB tiles) + transforms (z=2; 48KB)
    const size_t smem_kt = 49152;
    cudaFuncSetAttribute(knn_transform_kernel, cudaFuncAttributeMaxDynamicSharedMemorySize, (int)smem_kt);
    knn_transform_kernel<<<dim3(N / 16, BB, 3), 512, smem_kt>>>(
        pc1, pc2, i12, i21,
        feat1, feat2, t11_w, t11_b, t22_w, t22_b,
        q1, q2, r1, r2);

    const size_t smem = (size_t)SMEM_WORDS * 4;
    cudaFuncSetAttribute(cross_kernel<2,1>, cudaFuncAttributeMaxDynamicSharedMemorySize, (int)smem);
    cudaFuncSetAttribute(cross_kernel<1,0>, cudaFuncAttributeMaxDynamicSharedMemorySize, (int)smem);

    // cross 1 & 2 fused (grid.y = direction) with fp32 final-linear epilogue
    cross_kernel<2,1><<<dim3(BB * N / 32, 2), 256, smem>>>(
        i12, i21, pc1, pc2,
        q1, q2, r1, r2,
        pos1_w, pos1_b, mlp1_w1, mlp1_b1, mlp1_w2, mlp1_b2,
        t1_w, t1_b, t2_w, t2_b,
        f1, f2, out, out + (size_t)BB * 64 * N);

    // cross 3 (1 mlp layer), transposed direct write to output region 2
    cross_kernel<1,0><<<dim3(BB * N / 32, 1), 256, smem>>>(
        i12, i12, pc1, pc2,
        f1, f2, f1, f2,
        pos2_w, pos2_b, mlp2_w1, mlp2_b1, mlp2_w1, mlp2_b1,
        mlp2_w1, mlp2_b1, mlp2_w1, mlp2_b1,
        out + (size_t)2 * BB * 64 * N, out + (size_t)2 * BB * 64 * N,
        out + (size_t)2 * BB * 64 * N, out + (size_t)2 * BB * 64 * N);
}

// round 16
// speedup vs baseline: 1.1265x; 1.0063x over previous
#include <cuda_runtime.h>

#define N 8192
#define BB 2
#define CH 64
#define KNB 16
#define FULLMASK 0xffffffffu
typedef unsigned long long ull;
typedef unsigned int uint;

// ---------------- scratch (static device globals; no allocation) ----------------
__device__ float g_q1[BB*N*CH];
__device__ float g_q2[BB*N*CH];
__device__ float g_r1[BB*N*CH];
__device__ float g_r2[BB*N*CH];
__device__ float g_f1[BB*N*CH];
__device__ float g_f2[BB*N*CH];
__device__ int   g_i12[BB*N*KNB];
__device__ int   g_i21[BB*N*KNB];

__device__ __forceinline__ float leaky(float x) { return fmaxf(x, 0.1f * x); }

// ---------------- packed f32x2 helpers ----------------
__device__ __forceinline__ ull ffma2(ull a, ull b, ull c) {
    ull d; asm("fma.rn.f32x2 %0, %1, %2, %3;" : "=l"(d) : "l"(a), "l"(b), "l"(c)); return d;
}
__device__ __forceinline__ ull pk2(float x, float y) {
    ull r; asm("mov.b64 %0, {%1, %2};" : "=l"(r) : "f"(x), "f"(y)); return r;
}
__device__ __forceinline__ ull dup2(float x) {
    ull r; asm("mov.b64 %0, {%1, %1};" : "=l"(r) : "f"(x)); return r;
}
__device__ __forceinline__ void unpk2(float& lo, float& hi, ull v) {
    asm("mov.b64 {%0, %1}, %2;" : "=f"(lo), "=f"(hi) : "l"(v));
}

// ---------------- tf32 / mma / ldmatrix helpers (cross) ----------------
__device__ __forceinline__ uint tf32r(float x) {
    uint u; asm("cvt.rna.tf32.f32 %0, %1;" : "=r"(u) : "f"(x)); return u;
}
__device__ __forceinline__ void mma_tf32(float* d, uint a0, uint a1, uint a2, uint a3,
                                         uint b0, uint b1) {
    asm volatile(
        "mma.sync.aligned.m16n8k8.row.col.f32.tf32.tf32.f32 "
        "{%0,%1,%2,%3}, {%4,%5,%6,%7}, {%8,%9}, {%0,%1,%2,%3};"
        : "+f"(d[0]), "+f"(d[1]), "+f"(d[2]), "+f"(d[3])
        : "r"(a0), "r"(a1), "r"(a2), "r"(a3), "r"(b0), "r"(b1));
}
__device__ __forceinline__ void ldsm_x4(uint& r0, uint& r1, uint& r2, uint& r3, uint a) {
    asm volatile("ldmatrix.sync.aligned.m8n8.x4.shared.b16 {%0,%1,%2,%3}, [%4];"
        : "=r"(r0), "=r"(r1), "=r"(r2), "=r"(r3) : "r"(a));
}

// ================= fused KNN (z=0,1; 2 queries/warp) + 4-way transform (z=2) =================
#define TILE 2048   // 32KB tile -> 4 blocks/SM

__global__ __launch_bounds__(512, 4) void knn_transform_kernel(
    const float* __restrict__ pc1, const float* __restrict__ pc2,
    int* __restrict__ i12, int* __restrict__ i21,
    const float* __restrict__ f1g, const float* __restrict__ f2g,
    const float* __restrict__ w11, const float* __restrict__ b11,
    const float* __restrict__ w22, const float* __restrict__ b22,
    float* __restrict__ q1o, float* __restrict__ q2o,
    float* __restrict__ r1o, float* __restrict__ r2o)
{
    extern __shared__ char smraw[];
    const int tid = threadIdx.x;

    if (blockIdx.z == 2) {
        ull* s_wp  = (ull*)smraw;
        ull* s_f12 = s_wp + 4096;
        ull* s_f21 = s_f12 + 1024;
        const int b = blockIdx.y, n0 = blockIdx.x * 16;
        for (int i = tid; i < 4096; i += 512) {
            int m = i >> 6, c = i & 63;
            s_wp[c * 64 + m] = pk2(w11[i], w22[i]);
        }
        for (int i = tid; i < 1024; i += 512) {
            int c = i >> 4, np = i & 15;
            float a = f1g[(b * 64 + c) * N + n0 + np];
            float d = f2g[(b * 64 + c) * N + n0 + np];
            s_f12[i] = pk2(a, d);
            s_f21[i] = pk2(d, a);
        }
        __syncthreads();
        const int m = tid & 63, grp = tid >> 6;
        ull bq = pk2(b11[m], b22[m]);
        ull a0 = bq, a1 = bq, r0 = bq, r1v = bq;
        const int np = grp * 2;
        #pragma unroll 8
        for (int c = 0; c < 64; c++) {
            ull wv = s_wp[c * 64 + m];
            a0  = ffma2(s_f12[c * 16 + np],     wv, a0);
            a1  = ffma2(s_f12[c * 16 + np + 1], wv, a1);
            r0  = ffma2(s_f21[c * 16 + np],     wv, r0);
            r1v = ffma2(s_f21[c * 16 + np + 1], wv, r1v);
        }
        float v1, v2;
        int q = (b * N + n0 + np) * 64 + m;
        unpk2(v1, v2, a0);  q1o[q] = v1;      q2o[q] = v2;
        unpk2(v1, v2, a1);  q1o[q + 64] = v1; q2o[q + 64] = v2;
        unpk2(v1, v2, r0);  r1o[q] = v1;      r2o[q] = v2;
        unpk2(v1, v2, r1v); r1o[q + 64] = v1; r2o[q + 64] = v2;
        return;
    }

    if (blockIdx.x >= N / 32) return;
    ulonglong2* s_t0 = (ulonglong2*)smraw;
    ulonglong2* s_t1 = s_t0 + (TILE / 2);
    const int dir = blockIdx.z;
    const float* q  = dir ? pc2 : pc1;
    const float* db = dir ? pc1 : pc2;
    int* oi = dir ? i21 : i12;
    const int b = blockIdx.y;
    const int warp = tid >> 5, lane = tid & 31;
    const int nA = blockIdx.x * 32 + warp * 2;
    const int nB = nA + 1;
    const float* qb = q + b * 3 * N;
    const ull m2qAx = dup2(-2.0f * qb[nA]);
    const ull m2qAy = dup2(-2.0f * qb[N + nA]);
    const ull m2qAz = dup2(-2.0f * qb[2 * N + nA]);
    const ull m2qBx = dup2(-2.0f * qb[nB]);
    const ull m2qBy = dup2(-2.0f * qb[N + nB]);
    const ull m2qBz = dup2(-2.0f * qb[2 * N + nB]);
    const float* dbb = db + b * 3 * N;

    float bd = 3.0e38f;
    int bi = 0;
    float tauA = 3.0e38f, tauB = 3.0e38f;
    const bool halfA = (lane < 16);

    for (int t = 0; t < N; t += TILE) {
        __syncthreads();
        const float2* gx = (const float2*)(dbb + t);
        const float2* gy = (const float2*)(dbb + N + t);
        const float2* gz = (const float2*)(dbb + 2 * N + t);
        for (int i = tid; i < TILE / 2; i += 512) {
            float2 x = gx[i], y = gy[i], z = gz[i];
            float w0 = x.x * x.x + y.x * y.x + z.x * z.x;
            float w1 = x.y * x.y + y.y * y.y + z.y * z.y;
            ulonglong2 A, B;
            A.x = *(const ull*)&x; A.y = *(const ull*)&y;
            B.x = *(const ull*)&z; B.y = pk2(w0, w1);
            s_t0[i] = A; s_t1[i] = B;
        }
        __syncthreads();
        for (int p = 0; p < TILE / 2; p += 32) {
            ulonglong2 t0 = s_t0[p + lane];
            ulonglong2 t1 = s_t1[p + lane];
            ull dA = ffma2(t0.x, m2qAx, t1.y);
            dA = ffma2(t0.y, m2qAy, dA);
            dA = ffma2(t1.x, m2qAz, dA);
            ull dB = ffma2(t0.x, m2qBx, t1.y);
            dB = ffma2(t0.y, m2qBy, dB);
            dB = ffma2(t1.x, m2qBz, dB);
            float dA0, dA1, dB0, dB1;
            unpk2(dA0, dA1, dA);
            unpk2(dB0, dB1, dB);
            bool hit = (fminf(dA0, dA1) < tauA) | (fminf(dB0, dB1) < tauB);
            if (__ballot_sync(FULLMASK, hit)) {
                const int base = t + 2 * p;
                unsigned mA0 = __ballot_sync(FULLMASK, dA0 < tauA);
                unsigned mA1 = __ballot_sync(FULLMASK, dA1 < tauA);
                unsigned mB0 = __ballot_sync(FULLMASK, dB0 < tauB);
                unsigned mB1 = __ballot_sync(FULLMASK, dB1 < tauB);
                unsigned mm0 = halfA ? mA0 : mB0;
                unsigned mm1 = halfA ? mA1 : mB1;
                int n0it = max(__popc(mA0), __popc(mB0));
                for (int it = 0; it < n0it; it++) {
                    int src = __ffs(mm0) - 1;
                    float vA = __shfl_sync(FULLMASK, dA0, src & 31);
                    float vB = __shfl_sync(FULLMASK, dB0, src & 31);
                    float dd = halfA ? vA : vB;
                    float up  = __shfl_up_sync(FULLMASK, bd, 1, 16);
                    int   upi = __shfl_up_sync(FULLMASK, bi, 1, 16);
                    if ((lane & 15) == 0) up = -3.0e38f;
                    if (mm0 && bd > dd) {
                        bool tk = up > dd;
                        bd = tk ? up : dd;
                        bi = tk ? upi : base + 2 * src;
                    }
                    mm0 &= mm0 - 1;
                }
                int n1it = max(__popc(mA1), __popc(mB1));
                for (int it = 0; it < n1it; it++) {
                    int src = __ffs(mm1) - 1;
                    float vA = __shfl_sync(FULLMASK, dA1, src & 31);
                    float vB = __shfl_sync(FULLMASK, dB1, src & 31);
                    float dd = halfA ? vA : vB;
                    float up  = __shfl_up_sync(FULLMASK, bd, 1, 16);
                    int   upi = __shfl_up_sync(FULLMASK, bi, 1, 16);
                    if ((lane & 15) == 0) up = -3.0e38f;
                    if (mm1 && bd > dd) {
                        bool tk = up > dd;
                        bd = tk ? up : dd;
                        bi = tk ? upi : base + 2 * src + 1;
                    }
                    mm1 &= mm1 - 1;
                }
                tauA = __shfl_sync(FULLMASK, bd, 15);
                tauB = __shfl_sync(FULLMASK, bd, 31);
            }
        }
    }
    const int nOut = halfA ? nA : nB;
    oi[((b * N) + nOut) * 16 + (lane & 15)] = bi;
}

// ================= tf32 tensor-core cross12 (with fp32 final-linear epilogue) =================
// block = 256 threads = 8 warps; each warp: 4 queries, m16n8k8 tf32 MMA per query.
// smem (uint words):
#define U_W1 0          // 64*68
#define U_W2 4352       // 64*68
#define U_W3 8704       // 64*68 (fp32, epilogue)
#define U_PWT 13056     // 192
#define U_PB  13248     // 64
#define U_B1  13312     // 64
#define U_B2  13376     // 64
#define U_B3  13440     // 64
#define U_H   13504     // 8 warps * 16*68 = 8704
#define U_POOL 22208    // 8 warps * 256 = 2048
#define SMEM_WORDS 24256

__global__ __launch_bounds__(256) void cross12_kernel(
    const int* __restrict__ iA, const int* __restrict__ iB,
    const float* __restrict__ xA, const float* __restrict__ xB,
    const float* __restrict__ p1A, const float* __restrict__ p2A,
    const float* __restrict__ p1B, const float* __restrict__ p2B,
    const float* __restrict__ posw, const float* __restrict__ posb,
    const float* __restrict__ w1, const float* __restrict__ b1,
    const float* __restrict__ w2, const float* __restrict__ b2,
    const float* __restrict__ w3A, const float* __restrict__ b3A,
    const float* __restrict__ w3B, const float* __restrict__ b3B,
    float* __restrict__ obnA, float* __restrict__ obnB,
    float* __restrict__ ocnA, float* __restrict__ ocnB)
{
    extern __shared__ uint smu[];
    uint*  s_w1u = smu + U_W1;
    uint*  s_w2u = smu + U_W2;
    float* s_w3  = (float*)(smu + U_W3);
    float* s_pwt = (float*)(smu + U_PWT);
    float* s_pb  = (float*)(smu + U_PB);
    float* s_b1  = (float*)(smu + U_B1);
    float* s_b2  = (float*)(smu + U_B2);
    float* s_b3  = (float*)(smu + U_B3);
    uint*  s_hall = smu + U_H;
    float* s_pool = (float*)(smu + U_POOL);

    const int dir = blockIdx.y;
    const int* idx = dir ? iB : iA;
    const float* xyz1 = dir ? xB : xA;
    const float* xyz2 = dir ? xA : xB;
    const float* p1 = dir ? p1B : p1A;
    const float* p2 = dir ? p2B : p2A;
    const float* w3 = dir ? w3B : w3A;
    const float* b3 = dir ? b3B : b3A;
    float* obn = dir ? obnB : obnA;
    float* ocn = dir ? ocnB : ocnA;

    const int tid = threadIdx.x;
    for (int i = tid; i < 4096; i += 256) {
        int m = i >> 6, c = i & 63;
        s_w1u[m * 68 + c] = tf32r(w1[i]);
        s_w2u[m * 68 + c] = tf32r(w2[i]);
        s_w3[m * 68 + c] = w3[i];
    }
    if (tid < 192) s_pwt[tid] = posw[(tid & 63) * 3 + (tid >> 6)];
    if (tid < 64) {
        s_pb[tid] = posb[tid];
        s_b1[tid] = b1[tid];
        s_b2[tid] = b2[tid];
        s_b3[tid] = b3[tid];
    }
    __syncthreads();

    const int warp = tid >> 5, lane = tid & 31;
    const int g = lane >> 2, t = lane & 3;
    uint*  s_h  = s_hall + warp * 1088;   // 16 rows * 68
    float* s_pw = s_pool + warp * 256;    // 4 queries * 64
    const int wq0 = (blockIdx.x * 8 + warp) * 4;

    const int r8 = lane & 7, q8 = lane >> 3;
    const int rowA = r8 + ((q8 >> 1) << 3);
    const int cofA = (q8 & 1) * 4;
    const uint aAddr = (uint)__cvta_generic_to_shared(s_h + rowA * 68 + cofA);
    const int rB4 = ((q8 >> 1) << 3) + r8;
    const int cofB = (q8 & 1) * 4;
    const uint b1Addr = (uint)__cvta_generic_to_shared(s_w1u + rB4 * 68 + cofB);
    const uint b2Addr = (uint)__cvta_generic_to_shared(s_w2u + rB4 * 68 + cofB);

    const float pw0a = s_pwt[lane],      pw1a = s_pwt[64 + lane],  pw2a = s_pwt[128 + lane];
    const float pw0b = s_pwt[lane + 32], pw1b = s_pwt[96 + lane],  pw2b = s_pwt[160 + lane];
    const float pba = s_pb[lane], pbb = s_pb[lane + 32];

    for (int qi = 0; qi < 4; qi++) {
        const int q = wq0 + qi;
        const int b = q >> 13, n = q & (N - 1);
        const int myidx = idx[q * 16 + (lane & 15)];
        const float p1a = p1[q * 64 + lane];
        const float p1b = p1[q * 64 + 32 + lane];
        const float* x1b = xyz1 + b * 3 * N;
        const float qx = x1b[n], qy = x1b[N + n], qz = x1b[2 * N + n];
        const float* x2b = xyz2 + b * 3 * N;
        const float nx = x2b[myidx], ny = x2b[N + myidx], nz = x2b[2 * N + myidx];

        #pragma unroll
        for (int k = 0; k < 16; k++) {
            int j = __shfl_sync(FULLMASK, myidx, k);
            float dx = __shfl_sync(FULLMASK, nx, k) - qx;
            float dy = __shfl_sync(FULLMASK, ny, k) - qy;
            float dz = __shfl_sync(FULLMASK, nz, k) - qz;
            const float* p2r = p2 + ((size_t)((b << 13) + j)) * 64;
            float ga = p2r[lane], gb = p2r[lane + 32];
            float pa = pba + dx * pw0a + dy * pw1a + dz * pw2a;
            float pb = pbb + dx * pw0b + dy * pw1b + dz * pw2b;
            s_h[k * 68 + lane]      = tf32r(leaky(ga + p1a + pa));
            s_h[k * 68 + 32 + lane] = tf32r(leaky(gb + p1b + pb));
        }
        __syncwarp();

        float d[8][4];
        #pragma unroll
        for (int nt = 0; nt < 8; nt++) {
            float2 bv = *(const float2*)&s_b1[nt * 8 + t * 2];
            d[nt][0] = bv.x; d[nt][1] = bv.y; d[nt][2] = bv.x; d[nt][3] = bv.y;
        }
        #pragma unroll
        for (int ks = 0; ks < 8; ks++) {
            uint f0, f1, f2, f3;
            ldsm_x4(f0, f1, f2, f3, aAddr + ks * 32);
            #pragma unroll
            for (int nj = 0; nj < 4; nj++) {
                uint b0, b1v, b2v, b3v;
                ldsm_x4(b0, b1v, b2v, b3v, b1Addr + (nj * 16 * 68 + ks * 8) * 4);
                mma_tf32(d[2 * nj],     f0, f2, f1, f3, b0, b1v);
                mma_tf32(d[2 * nj + 1], f0, f2, f1, f3, b2v, b3v);
            }
        }

        __syncwarp();
        #pragma unroll
        for (int nt = 0; nt < 8; nt++) {
            int c0 = nt * 8 + t * 2;
            s_h[g * 68 + c0]           = tf32r(leaky(d[nt][0]));
            s_h[g * 68 + c0 + 1]       = tf32r(leaky(d[nt][1]));
            s_h[(g + 8) * 68 + c0]     = tf32r(leaky(d[nt][2]));
            s_h[(g + 8) * 68 + c0 + 1] = tf32r(leaky(d[nt][3]));
        }
        __syncwarp();
        #pragma unroll
        for (int nt = 0; nt < 8; nt++) {
            float2 bv = *(const float2*)&s_b2[nt * 8 + t * 2];
            d[nt][0] = bv.x; d[nt][1] = bv.y; d[nt][2] = bv.x; d[nt][3] = bv.y;
        }
        #pragma unroll
        for (int ks = 0; ks < 8; ks++) {
            uint f0, f1, f2, f3;
            ldsm_x4(f0, f1, f2, f3, aAddr + ks * 32);
            #pragma unroll
            for (int nj = 0; nj < 4; nj++) {
                uint b0, b1v, b2v, b3v;
                ldsm_x4(b0, b1v, b2v, b3v, b2Addr + (nj * 16 * 68 + ks * 8) * 4);
                mma_tf32(d[2 * nj],     f0, f2, f1, f3, b0, b1v);
                mma_tf32(d[2 * nj + 1], f0, f2, f1, f3, b2v, b3v);
            }
        }

        #pragma unroll
        for (int nt = 0; nt < 8; nt++) {
            float u0 = fmaxf(d[nt][0], d[nt][2]);
            float u1 = fmaxf(d[nt][1], d[nt][3]);
            u0 = fmaxf(u0, __shfl_xor_sync(FULLMASK, u0, 4));
            u1 = fmaxf(u1, __shfl_xor_sync(FULLMASK, u1, 4));
            u0 = fmaxf(u0, __shfl_xor_sync(FULLMASK, u0, 8));
            u1 = fmaxf(u1, __shfl_xor_sync(FULLMASK, u1, 8));
            u0 = fmaxf(u0, __shfl_xor_sync(FULLMASK, u0, 16));
            u1 = fmaxf(u1, __shfl_xor_sync(FULLMASK, u1, 16));
            if (nt == g) {
                s_pw[qi * 64 + g * 8 + t * 2]     = leaky(u0);
                s_pw[qi * 64 + g * 8 + t * 2 + 1] = leaky(u1);
            }
        }
        __syncwarp();
    }

    // fp32 final linear: lane owns channels (lane, lane+32); 4 queries
    float acc[4][2];
    #pragma unroll
    for (int q4 = 0; q4 < 4; q4++) { acc[q4][0] = s_b3[lane]; acc[q4][1] = s_b3[lane + 32]; }
    #pragma unroll
    for (int jb = 0; jb < 16; jb++) {
        float4 wa = *(const float4*)&s_w3[lane * 68 + jb * 4];
        float4 wb = *(const float4*)&s_w3[(lane + 32) * 68 + jb * 4];
        #pragma unroll
        for (int q4 = 0; q4 < 4; q4++) {
            float4 hv = *(const float4*)&s_pw[q4 * 64 + jb * 4];
            acc[q4][0] += hv.x * wa.x + hv.y * wa.y + hv.z * wa.z + hv.w * wa.w;
            acc[q4][1] += hv.x * wb.x + hv.y * wb.y + hv.z * wb.z + hv.w * wb.w;
        }
    }
    #pragma unroll
    for (int q4 = 0; q4 < 4; q4++) {
        const int q = wq0 + q4;
        const int b = q >> 13, n = q & (N - 1);
        obn[q * 64 + lane]      = acc[q4][0];
        obn[q * 64 + 32 + lane] = acc[q4][1];
        ocn[((b * 64) + lane) * N + n]      = acc[q4][0];
        ocn[((b * 64) + lane + 32) * N + n] = acc[q4][1];
    }
}

// ================= compact cross3: 1 MLP layer, transposed write (R12-measured 49us) =================
// smem (uint words): W1=0..4352, PWT=4352, PB=4544, B1=4608, H=4736..13440  (53.8KB)
#define C3_W1  0
#define C3_PWT 4352
#define C3_PB  4544
#define C3_B1  4608
#define C3_H   4736
#define C3_WORDS 13440

__global__ __launch_bounds__(256, 3) void cross3_kernel(
    const int* __restrict__ idx,
    const float* __restrict__ xyz1, const float* __restrict__ xyz2,
    const float* __restrict__ p1, const float* __restrict__ p2,
    const float* __restrict__ posw, const float* __restrict__ posb,
    const float* __restrict__ w1, const float* __restrict__ b1,
    float* __restrict__ ocn)
{
    extern __shared__ uint smu[];
    uint*  s_w1u = smu + C3_W1;
    float* s_pwt = (float*)(smu + C3_PWT);
    float* s_pb  = (float*)(smu + C3_PB);
    float* s_b1  = (float*)(smu + C3_B1);
    uint*  s_hall = smu + C3_H;

    const int tid = threadIdx.x;
    for (int i = tid; i < 4096; i += 256) {
        int m = i >> 6, c = i & 63;
        s_w1u[m * 68 + c] = tf32r(w1[i]);
    }
    if (tid < 192) s_pwt[tid] = posw[(tid & 63) * 3 + (tid >> 6)];
    if (tid < 64) {
        s_pb[tid] = posb[tid];
        s_b1[tid] = b1[tid];
    }
    __syncthreads();

    const int warp = tid >> 5, lane = tid & 31;
    const int g = lane >> 2, t = lane & 3;
    uint* s_h = s_hall + warp * 1088;
    const int wq0 = (blockIdx.x * 8 + warp) * 4;

    const int r8 = lane & 7, q8 = lane >> 3;
    const int rowA = r8 + ((q8 >> 1) << 3);
    const int cofA = (q8 & 1) * 4;
    const uint aAddr = (uint)__cvta_generic_to_shared(s_h + rowA * 68 + cofA);
    const int rB4 = ((q8 >> 1) << 3) + r8;
    const int cofB = (q8 & 1) * 4;
    const uint b1Addr = (uint)__cvta_generic_to_shared(s_w1u + rB4 * 68 + cofB);

    const float pw0a = s_pwt[lane],      pw1a = s_pwt[64 + lane],  pw2a = s_pwt[128 + lane];
    const float pw0b = s_pwt[lane + 32], pw1b = s_pwt[96 + lane],  pw2b = s_pwt[160 + lane];
    const float pba = s_pb[lane], pbb = s_pb[lane + 32];

    for (int qi = 0; qi < 4; qi++) {
        const int q = wq0 + qi;
        const int b = q >> 13, n = q & (N - 1);
        const int myidx = idx[q * 16 + (lane & 15)];
        const float p1a = p1[q * 64 + lane];
        const float p1b = p1[q * 64 + 32 + lane];
        const float* x1b = xyz1 + b * 3 * N;
        const float qx = x1b[n], qy = x1b[N + n], qz = x1b[2 * N + n];
        const float* x2b = xyz2 + b * 3 * N;
        const float nx = x2b[myidx], ny = x2b[N + myidx], nz = x2b[2 * N + myidx];

        #pragma unroll
        for (int k = 0; k < 16; k++) {
            int j = __shfl_sync(FULLMASK, myidx, k);
            float dx = __shfl_sync(FULLMASK, nx, k) - qx;
            float dy = __shfl_sync(FULLMASK, ny, k) - qy;
            float dz = __shfl_sync(FULLMASK, nz, k) - qz;
            const float* p2r = p2 + ((size_t)((b << 13) + j)) * 64;
            float ga = p2r[lane], gb = p2r[lane + 32];
            float pa = pba + dx * pw0a + dy * pw1a + dz * pw2a;
            float pb = pbb + dx * pw0b + dy * pw1b + dz * pw2b;
            s_h[k * 68 + lane]      = tf32r(leaky(ga + p1a + pa));
            s_h[k * 68 + 32 + lane] = tf32r(leaky(gb + p1b + pb));
        }
        __syncwarp();

        float d[8][4];
        #pragma unroll
        for (int nt = 0; nt < 8; nt++) {
            float2 bv = *(const float2*)&s_b1[nt * 8 + t * 2];
            d[nt][0] = bv.x; d[nt][1] = bv.y; d[nt][2] = bv.x; d[nt][3] = bv.y;
        }
        #pragma unroll
        for (int ks = 0; ks < 8; ks++) {
            uint f0, f1, f2, f3;
            ldsm_x4(f0, f1, f2, f3, aAddr + ks * 32);
            #pragma unroll
            for (int nj = 0; nj < 4; nj++) {
                uint b0, b1v, b2v, b3v;
                ldsm_x4(b0, b1v, b2v, b3v, b1Addr + (nj * 16 * 68 + ks * 8) * 4);
                mma_tf32(d[2 * nj],     f0, f2, f1, f3, b0, b1v);
                mma_tf32(d[2 * nj + 1], f0, f2, f1, f3, b2v, b3v);
            }
        }

        #pragma unroll
        for (int nt = 0; nt < 8; nt++) {
            float u0 = fmaxf(d[nt][0], d[nt][2]);
            float u1 = fmaxf(d[nt][1], d[nt][3]);
            u0 = fmaxf(u0, __shfl_xor_sync(FULLMASK, u0, 4));
            u1 = fmaxf(u1, __shfl_xor_sync(FULLMASK, u1, 4));
            u0 = fmaxf(u0, __shfl_xor_sync(FULLMASK, u0, 8));
            u1 = fmaxf(u1, __shfl_xor_sync(FULLMASK, u1, 8));
            u0 = fmaxf(u0, __shfl_xor_sync(FULLMASK, u0, 16));
            u1 = fmaxf(u1, __shfl_xor_sync(FULLMASK, u1, 16));
            if (nt == g) {
                ocn[((b * 64) + g * 8 + t * 2) * N + n]     = leaky(u0);
                ocn[((b * 64) + g * 8 + t * 2 + 1) * N + n] = leaky(u1);
            }
        }
        __syncwarp();
    }
}

// ---------------- launch ----------------
extern "C" void kernel_launch(void* const* d_in, const int* in_sizes, int n_in,
                              void* d_out, int out_size)
{
    const float* pc1     = (const float*)d_in[0];
    const float* pc2     = (const float*)d_in[1];
    const float* feat1   = (const float*)d_in[2];
    const float* feat2   = (const float*)d_in[3];
    const float* t11_w   = (const float*)d_in[4];
    const float* t11_b   = (const float*)d_in[5];
    const float* t22_w   = (const float*)d_in[6];
    const float* t22_b   = (const float*)d_in[7];
    const float* pos1_w  = (const float*)d_in[8];
    const float* pos1_b  = (const float*)d_in[9];
    const float* mlp1_w1 = (const float*)d_in[10];
    const float* mlp1_b1 = (const float*)d_in[11];
    const float* mlp1_w2 = (const float*)d_in[12];
    const float* mlp1_b2 = (const float*)d_in[13];
    const float* t1_w    = (const float*)d_in[14];
    const float* t1_b    = (const float*)d_in[15];
    const float* t2_w    = (const float*)d_in[16];
    const float* t2_b    = (const float*)d_in[17];
    const float* pos2_w  = (const float*)d_in[18];
    const float* pos2_b  = (const float*)d_in[19];
    const float* mlp2_w1 = (const float*)d_in[20];
    const float* mlp2_b1 = (const float*)d_in[21];
    float* out = (float*)d_out;

    float *q1, *q2, *r1, *r2, *f1, *f2;
    int *i12, *i21;
    cudaGetSymbolAddress((void**)&q1, g_q1);
    cudaGetSymbolAddress((void**)&q2, g_q2);
    cudaGetSymbolAddress((void**)&r1, g_r1);
    cudaGetSymbolAddress((void**)&r2, g_r2);
    cudaGetSymbolAddress((void**)&f1, g_f1);
    cudaGetSymbolAddress((void**)&f2, g_f2);
    cudaGetSymbolAddress((void**)&i12, g_i12);
    cudaGetSymbolAddress((void**)&i21, g_i21);

    // fused KNN (z=0,1; 32KB tiles) + transforms (z=2; 48KB)
    const size_t smem_kt = 49152;
    cudaFuncSetAttribute(knn_transform_kernel, cudaFuncAttributeMaxDynamicSharedMemorySize, (int)smem_kt);
    knn_transform_kernel<<<dim3(N / 16, BB, 3), 512, smem_kt>>>(
        pc1, pc2, i12, i21,
        feat1, feat2, t11_w, t11_b, t22_w, t22_b,
        q1, q2, r1, r2);

    const size_t smem12 = (size_t)SMEM_WORDS * 4;
    const size_t smem3  = (size_t)C3_WORDS * 4;
    cudaFuncSetAttribute(cross12_kernel, cudaFuncAttributeMaxDynamicSharedMemorySize, (int)smem12);
    cudaFuncSetAttribute(cross3_kernel,  cudaFuncAttributeMaxDynamicSharedMemorySize, (int)smem3);

    // cross 1 & 2 fused (grid.y = direction) with fp32 final-linear epilogue
    cross12_kernel<<<dim3(BB * N / 32, 2), 256, smem12>>>(
        i12, i21, pc1, pc2,
        q1, q2, r1, r2,
        pos1_w, pos1_b, mlp1_w1, mlp1_b1, mlp1_w2, mlp1_b2,
        t1_w, t1_b, t2_w, t2_b,
        f1, f2, out, out + (size_t)BB * 64 * N);

    // cross 3 (compact: 1 mlp layer, 53.8KB smem, 3 blocks/SM), transposed direct write
    cross3_kernel<<<BB * N / 32, 256, smem3>>>(
        i12, pc1, pc2, f1, f2,
        pos2_w, pos2_b, mlp2_w1, mlp2_b1,
        out + (size_t)2 * BB * 64 * N);
}